// round 12
// baseline (speedup 1.0000x reference)
#include <cuda_runtime.h>
#include <cuda_bf16.h>
#include <stdint.h>

// Problem constants
#define BATCH   4
#define SEQ     2048
#define DMODEL  1024
#define NHEAD   16
#define HDIM    64
#define BHTOT   (BATCH * NHEAD)    // 64
#define MROWS   (BATCH * SEQ)      // 8192

// ---------------------------------------------------------------------------
// Scratch (static device globals — no allocation allowed)
// ---------------------------------------------------------------------------
__device__ __nv_bfloat16 g_xh[(size_t)MROWS * DMODEL];
__device__ __nv_bfloat16 g_xl[(size_t)MROWS * DMODEL];
__device__ __nv_bfloat16 g_wqh[(size_t)DMODEL * DMODEL];
__device__ __nv_bfloat16 g_wql[(size_t)DMODEL * DMODEL];
__device__ __nv_bfloat16 g_wkh[(size_t)DMODEL * DMODEL];
__device__ __nv_bfloat16 g_wkl[(size_t)DMODEL * DMODEL];
__device__ __nv_bfloat16 g_wvh[(size_t)DMODEL * DMODEL];
__device__ __nv_bfloat16 g_wvl[(size_t)DMODEL * DMODEL];
__device__ __nv_bfloat16 g_woh[(size_t)DMODEL * DMODEL];
__device__ __nv_bfloat16 g_wol[(size_t)DMODEL * DMODEL];
// Q/K/V in split-bf16, layout [bh][s][hd]
__device__ __nv_bfloat16 g_qh[(size_t)BHTOT * SEQ * HDIM];
__device__ __nv_bfloat16 g_ql[(size_t)BHTOT * SEQ * HDIM];
__device__ __nv_bfloat16 g_kh[(size_t)BHTOT * SEQ * HDIM];
__device__ __nv_bfloat16 g_kl[(size_t)BHTOT * SEQ * HDIM];
__device__ __nv_bfloat16 g_vh[(size_t)BHTOT * SEQ * HDIM];
__device__ __nv_bfloat16 g_vl[(size_t)BHTOT * SEQ * HDIM];
__device__ __nv_bfloat16 g_cxh[(size_t)MROWS * DMODEL];
__device__ __nv_bfloat16 g_cxl[(size_t)MROWS * DMODEL];

// ---------------------------------------------------------------------------
// Helpers
// ---------------------------------------------------------------------------
static __device__ __forceinline__ uint32_t s2u(const void* p) {
    uint32_t a;
    asm("{ .reg .u64 t; cvta.to.shared.u64 t, %1; cvt.u32.u64 %0, t; }"
        : "=r"(a) : "l"(p));
    return a;
}

#define CPA16(dst, src) \
    asm volatile("cp.async.cg.shared.global [%0], [%1], 16;" :: "r"(dst), "l"(src))
#define CP_COMMIT() asm volatile("cp.async.commit_group;" ::: "memory")
#define CP_WAIT(n)  asm volatile("cp.async.wait_group %0;" :: "n"(n) : "memory")

#define LDM4(r0, r1, r2, r3, a) \
    asm volatile("ldmatrix.sync.aligned.m8n8.x4.shared.b16 {%0,%1,%2,%3}, [%4];" \
                 : "=r"(r0), "=r"(r1), "=r"(r2), "=r"(r3) : "r"(a))
#define LDM2(r0, r1, a) \
    asm volatile("ldmatrix.sync.aligned.m8n8.x2.shared.b16 {%0,%1}, [%2];" \
                 : "=r"(r0), "=r"(r1) : "r"(a))
#define LDM4T(r0, r1, r2, r3, a) \
    asm volatile("ldmatrix.sync.aligned.m8n8.x4.trans.shared.b16 {%0,%1,%2,%3}, [%4];" \
                 : "=r"(r0), "=r"(r1), "=r"(r2), "=r"(r3) : "r"(a))

#define MMA16816(c, a0, a1, a2, a3, b0, b1) \
    asm volatile("mma.sync.aligned.m16n8k16.row.col.f32.bf16.bf16.f32 " \
                 "{%0,%1,%2,%3}, {%4,%5,%6,%7}, {%8,%9}, {%0,%1,%2,%3};" \
                 : "+f"((c)[0]), "+f"((c)[1]), "+f"((c)[2]), "+f"((c)[3]) \
                 : "r"(a0), "r"(a1), "r"(a2), "r"(a3), "r"(b0), "r"(b1))

static __device__ __forceinline__ float ex2f(float x) {
    float y;
    asm("ex2.approx.ftz.f32 %0, %1;" : "=f"(y) : "f"(x));
    return y;
}
static __device__ __forceinline__ uint32_t packbf(float a, float b) {
    __nv_bfloat162 t = __floats2bfloat162_rn(a, b);
    return *reinterpret_cast<uint32_t*>(&t);
}
static __device__ __forceinline__ uint32_t packres(float a, float b) {
    float ra = a - __bfloat162float(__float2bfloat16(a));
    float rb = b - __bfloat162float(__float2bfloat16(b));
    return packbf(ra, rb);
}

// XOR swizzle for 64B-row tiles: row r, 16B-chunk c (0..3)
static __device__ __forceinline__ uint32_t swz64(int r, int c) {
    return (uint32_t)(r * 64 + ((c ^ ((r >> 1) & 3)) << 4));
}

// ---------------------------------------------------------------------------
// Pre-pass: split fp32 -> bf16 hi/lo (elementwise)
// ---------------------------------------------------------------------------
__global__ void __launch_bounds__(256)
conv_split(const float4* __restrict__ X, __nv_bfloat162* __restrict__ H,
           __nv_bfloat162* __restrict__ L)
{
    int i = blockIdx.x * 256 + threadIdx.x;
    float4 v = X[i];
    H[2 * i]     = __floats2bfloat162_rn(v.x, v.y);
    H[2 * i + 1] = __floats2bfloat162_rn(v.z, v.w);
    uint32_t l0 = packres(v.x, v.y), l1 = packres(v.z, v.w);
    L[2 * i]     = *reinterpret_cast<__nv_bfloat162*>(&l0);
    L[2 * i + 1] = *reinterpret_cast<__nv_bfloat162*>(&l1);
}

// ---------------------------------------------------------------------------
// Pre-pass: W[k][n] fp32 -> Wt[n][k] bf16 hi/lo (transpose + split),
// all 4 weight matrices in one launch (blockIdx.z selects).
// ---------------------------------------------------------------------------
struct WTp {
    const float* w[4];
    __nv_bfloat16* th[4];
    __nv_bfloat16* tl[4];
};

__global__ void __launch_bounds__(256)
conv_wT(WTp p)
{
    __shared__ float t[32][33];
    const int z = blockIdx.z;
    const float* __restrict__ W = p.w[z];
    __nv_bfloat16* __restrict__ Th = p.th[z];
    __nv_bfloat16* __restrict__ Tl = p.tl[z];
    const int n0 = blockIdx.x * 32, k0 = blockIdx.y * 32;
    const int tx = threadIdx.x, ty = threadIdx.y;   // 32 x 8
#pragma unroll
    for (int i = 0; i < 4; i++)
        t[ty + i * 8][tx] = W[(size_t)(k0 + ty + i * 8) * DMODEL + n0 + tx];
    __syncthreads();
#pragma unroll
    for (int i = 0; i < 4; i++) {
        float v = t[tx][ty + i * 8];
        __nv_bfloat16 h = __float2bfloat16(v);
        size_t o = (size_t)(n0 + ty + i * 8) * DMODEL + k0 + tx;
        Th[o] = h;
        Tl[o] = __float2bfloat16(v - __bfloat162float(h));
    }
}

// ---------------------------------------------------------------------------
// HMMA split-bf16 GEMM body: C[8192, 1024] = (Ah+Al) @ (Bh+Bl)^T
// CTA tile 128x256, 8 warps (2x4), warp tile 64x64 (4 mt x 8 nt).
// Better reuse than 128x128: A-frag duplication /2, L2 traffic 512->384MB.
// XOR-swizzled 64B rows, 3-stage cp.async ring, ONE sync/stage, loads
// issued BEFORE the wait. 1 CTA/SM (regs ~200, smem 144KB).
// SCAT=true: split-bf16 out in [bh][s][hd] (QKV). SCAT=false: fp32 + bias.
// ---------------------------------------------------------------------------
#define ATILE   8192                        // 128 rows x 64B
#define BTILE   16384                       // 256 rows x 64B
#define STAGE_B (2 * ATILE + 2 * BTILE)     // 49152
#define GM_SMEM (3 * STAGE_B)               // 147456

template <bool SCAT>
static __device__ __forceinline__ void
gemm_body(const __nv_bfloat16* __restrict__ Ah, const __nv_bfloat16* __restrict__ Al,
          const __nv_bfloat16* __restrict__ Bh, const __nv_bfloat16* __restrict__ Bl,
          float* __restrict__ C, const float* __restrict__ bias,
          __nv_bfloat16* __restrict__ Ch, __nv_bfloat16* __restrict__ Cl)
{
    extern __shared__ char smem[];
    const uint32_t sb = s2u(smem);
    const int tid = threadIdx.x;
    const int wid = tid >> 5, lane = tid & 31;
    const int warp_m = wid & 1;            // 0..1 (64 rows each)
    const int warp_n = wid >> 1;           // 0..3 (64 cols each)
    const int bm = blockIdx.y * 128;
    const int bn = blockIdx.x * 256;

    float acc[4][8][4];
#pragma unroll
    for (int i = 0; i < 4; i++)
#pragma unroll
        for (int j = 0; j < 8; j++)
#pragma unroll
            for (int q = 0; q < 4; q++) acc[i][j][q] = 0.f;

    auto load_stage = [&](int s, int buf) {
        const int k0 = s * 32;
        const uint32_t base = sb + buf * STAGE_B;
        // A: 128 rows x 4 chunks, hi + lo (512 chunks each)
#pragma unroll
        for (int i = 0; i < 2; i++) {
            int idx = tid + i * 256;
            int r = idx >> 2, c = idx & 3;
            uint32_t off = swz64(r, c);
            const size_t ga = (size_t)(bm + r) * DMODEL + k0 + c * 8;
            CPA16(base + off,         Ah + ga);
            CPA16(base + ATILE + off, Al + ga);
        }
        // B: 256 rows x 4 chunks, hi + lo (1024 chunks each)
#pragma unroll
        for (int i = 0; i < 4; i++) {
            int idx = tid + i * 256;
            int r = idx >> 2, c = idx & 3;
            uint32_t off = swz64(r, c);
            const size_t gb = (size_t)(bn + r) * DMODEL + k0 + c * 8;
            CPA16(base + 2 * ATILE + off,         Bh + gb);
            CPA16(base + 2 * ATILE + BTILE + off, Bl + gb);
        }
        CP_COMMIT();
    };

    load_stage(0, 0);

    const int a_row = warp_m * 64 + (lane & 15);
    const int a_c   = (lane >> 4);             // + kk*2
    const int b_row = warp_n * 64 + (lane & 7);
    const int b_c   = ((lane >> 3) & 1);       // + kk*2

    const int NSTAGE = DMODEL / 32;   // 32

    for (int s = 0; s < NSTAGE; s++) {
        if (s + 1 < NSTAGE) {
            load_stage(s + 1, (s + 1) % 3);    // issue BEFORE wait
            CP_WAIT(1);                        // stage s resident
        } else {
            CP_WAIT(0);
        }
        __syncthreads();

        const uint32_t base = sb + (s % 3) * STAGE_B;
#pragma unroll
        for (int kk = 0; kk < 2; kk++) {
            uint32_t ah[4][4], al[4][4];
#pragma unroll
            for (int mt = 0; mt < 4; mt++) {
                uint32_t ra = base + swz64(a_row + mt * 16, a_c + kk * 2);
                LDM4(ah[mt][0], ah[mt][1], ah[mt][2], ah[mt][3], ra);
                LDM4(al[mt][0], al[mt][1], al[mt][2], al[mt][3], ra + ATILE);
            }
#pragma unroll
            for (int nt = 0; nt < 8; nt++) {
                uint32_t bh0, bh1, bl0, bl1;
                uint32_t rb = base + 2 * ATILE + swz64(b_row + nt * 8, b_c + kk * 2);
                LDM2(bh0, bh1, rb);
                LDM2(bl0, bl1, rb + BTILE);
#pragma unroll
                for (int mt = 0; mt < 4; mt++) {
                    MMA16816(acc[mt][nt], ah[mt][0], ah[mt][1], ah[mt][2], ah[mt][3],
                             bh0, bh1);
                    MMA16816(acc[mt][nt], ah[mt][0], ah[mt][1], ah[mt][2], ah[mt][3],
                             bl0, bl1);
                    MMA16816(acc[mt][nt], al[mt][0], al[mt][1], al[mt][2], al[mt][3],
                             bh0, bh1);
                }
            }
        }
    }

    // Epilogue
    const int r0 = bm + warp_m * 64 + (lane >> 2);
    const int c0 = bn + warp_n * 64 + (lane & 3) * 2;
#pragma unroll
    for (int mt = 0; mt < 4; mt++) {
#pragma unroll
        for (int nt = 0; nt < 8; nt++) {
            const int row = r0 + mt * 16;
            const int col = c0 + nt * 8;
            if (SCAT) {
                const int h = col >> 6, hd = col & 63;
#pragma unroll
                for (int half = 0; half < 2; half++) {
                    const int rr = row + half * 8;
                    const int b = rr >> 11, sq = rr & 2047;
                    size_t o = (((size_t)(b * NHEAD + h) * SEQ + sq) * HDIM + hd);
                    float v0 = acc[mt][nt][2 * half], v1 = acc[mt][nt][2 * half + 1];
                    *(uint32_t*)(Ch + o) = packbf(v0, v1);
                    *(uint32_t*)(Cl + o) = packres(v0, v1);
                }
            } else {
                float2 bv = *(const float2*)(bias + col);
#pragma unroll
                for (int half = 0; half < 2; half++) {
                    const int rr = row + half * 8;
                    float* dst = C + (size_t)rr * DMODEL + col;
                    *(float2*)dst = make_float2(acc[mt][nt][2 * half] + bv.x,
                                                acc[mt][nt][2 * half + 1] + bv.y);
                }
            }
        }
    }
}

struct QKVp {
    const __nv_bfloat16* bh[3];
    const __nv_bfloat16* bl[3];
    __nv_bfloat16* ch[3];
    __nv_bfloat16* cl[3];
};

__global__ void __launch_bounds__(256, 1)
gemm_qkv(const __nv_bfloat16* __restrict__ Ah, const __nv_bfloat16* __restrict__ Al,
         QKVp p)
{
    const int z = blockIdx.z;
    gemm_body<true>(Ah, Al, p.bh[z], p.bl[z], nullptr, nullptr, p.ch[z], p.cl[z]);
}

__global__ void __launch_bounds__(256, 1)
gemm_out(const __nv_bfloat16* __restrict__ Ah, const __nv_bfloat16* __restrict__ Al,
         const __nv_bfloat16* __restrict__ Bh, const __nv_bfloat16* __restrict__ Bl,
         float* __restrict__ C, const float* __restrict__ bias)
{
    gemm_body<false>(Ah, Al, Bh, Bl, C, bias, nullptr, nullptr);
}

// ---------------------------------------------------------------------------
// HMMA causal flash attention (unchanged from R11 winner): split-bf16
// 3-term, 4 warps x 32 query rows, per-16-key-chunk interleave, K/V
// double-buffered, LPT scheduling.
// ---------------------------------------------------------------------------
#define QKS 0.18033688f   // log2(e) / sqrt(64)
#define SKB 144           // padded row stride in bytes (72 bf16)
#define AQH_OFF 0
#define AQL_OFF 18432
#define KV_OFF  36864     // start of KV buffers
#define KVB     36864     // bytes per KV buffer (KH, KL, VH, VL @ 9216 each)
#define ATT_SMEM (KV_OFF + 2 * KVB)   // 110592

__global__ void __launch_bounds__(128, 2)
attn_hmma()
{
    extern __shared__ char smem[];
    const uint32_t sb = s2u(smem);
    const int tid = threadIdx.x, wid = tid >> 5, lane = tid & 31;
    const int qt = (int)(gridDim.x - 1 - blockIdx.x);   // LPT: long CTAs first
    const int bh = blockIdx.y;

    // async-load Q tile (hi+lo): 128 rows x 64 bf16, 128 threads
    {
        const __nv_bfloat16* qh = g_qh + ((size_t)bh * SEQ + qt * 128) * HDIM;
        const __nv_bfloat16* ql = g_ql + ((size_t)bh * SEQ + qt * 128) * HDIM;
#pragma unroll
        for (int i = 0; i < 8; i++) {
            int c = tid + i * 128;
            int r = c >> 3, ch = c & 7;
            uint32_t o = (uint32_t)(r * SKB + ch * 16);
            CPA16(sb + AQH_OFF + o, qh + r * HDIM + ch * 8);
            CPA16(sb + AQL_OFF + o, ql + r * HDIM + ch * 8);
        }
        CP_COMMIT();
    }

    auto load_kv = [&](int kt, int buf) {
        const size_t gbase = ((size_t)bh * SEQ + kt * 64) * HDIM;
        const uint32_t base = sb + KV_OFF + buf * KVB;
#pragma unroll
        for (int i = 0; i < 4; i++) {
            int c = tid + i * 128;            // 0..511
            int r = c >> 3, ch = c & 7;
            uint32_t o = (uint32_t)(r * SKB + ch * 16);
            const int g = r * HDIM + ch * 8;
            CPA16(base + o,             g_kh + gbase + g);
            CPA16(base + 9216 + o,      g_kl + gbase + g);
            CPA16(base + 18432 + o,     g_vh + gbase + g);
            CPA16(base + 27648 + o,     g_vl + gbase + g);
        }
        CP_COMMIT();
    };

    const int ktiles = 2 * qt + 2;
    load_kv(0, 0);
    CP_WAIT(0);
    __syncthreads();

    // Q fragments: 2 m16 tiles per warp (rows wid*32 + mt*16), never overwritten
    uint32_t qfh[2][4][4], qfl[2][4][4];
#pragma unroll
    for (int mt = 0; mt < 2; mt++) {
        uint32_t ra = sb + AQH_OFF
                    + (uint32_t)(wid * 32 + mt * 16 + (lane & 15)) * SKB
                    + (uint32_t)(lane >> 4) * 16;
        uint32_t rl = ra + (AQL_OFF - AQH_OFF);
#pragma unroll
        for (int ks = 0; ks < 4; ks++) {
            LDM4(qfh[mt][ks][0], qfh[mt][ks][1], qfh[mt][ks][2], qfh[mt][ks][3],
                 ra + ks * 32);
            LDM4(qfl[mt][ks][0], qfl[mt][ks][1], qfl[mt][ks][2], qfl[mt][ks][3],
                 rl + ks * 32);
        }
    }

    float ctx[2][8][4];
#pragma unroll
    for (int mt = 0; mt < 2; mt++)
#pragma unroll
        for (int d = 0; d < 8; d++)
#pragma unroll
            for (int q = 0; q < 4; q++) ctx[mt][d][q] = 0.f;
    float ls0[2] = {0.f, 0.f}, ls1[2] = {0.f, 0.f};

    const int row_hi = qt * 128 + wid * 32 + 31;
    int rq0[2], rq1[2];
#pragma unroll
    for (int mt = 0; mt < 2; mt++) {
        rq0[mt] = qt * 128 + wid * 32 + mt * 16 + (lane >> 2);
        rq1[mt] = rq0[mt] + 8;
    }

    int buf = 0;
    for (int kt = 0; kt < ktiles; kt++) {
        if (kt + 1 < ktiles) load_kv(kt + 1, buf ^ 1);

        if (kt * 64 <= row_hi) {
            const uint32_t bbase = sb + KV_OFF + buf * KVB;

#pragma unroll
            for (int ck = 0; ck < 4; ck++) {        // 16-key chunks
                if (kt * 64 + ck * 16 > row_hi) break;

                // ---- QK^T for this chunk: 2 nt x 2 mt ----
                float sc[2][2][4];                   // [mt][ntl][4]
#pragma unroll
                for (int mt = 0; mt < 2; mt++)
#pragma unroll
                    for (int ntl = 0; ntl < 2; ntl++)
#pragma unroll
                        for (int q = 0; q < 4; q++) sc[mt][ntl][q] = 0.f;

#pragma unroll
                for (int ntl = 0; ntl < 2; ntl++) {
                    const int nt = ck * 2 + ntl;
                    uint32_t kf[8], lf[8];
                    uint32_t rb = bbase + (uint32_t)(nt * 8 + (lane & 7)) * SKB
                                + (uint32_t)(lane >> 3) * 16;
                    LDM4(kf[0], kf[1], kf[2], kf[3], rb);
                    LDM4(kf[4], kf[5], kf[6], kf[7], rb + 64);
                    uint32_t rbl = rb + 9216;
                    LDM4(lf[0], lf[1], lf[2], lf[3], rbl);
                    LDM4(lf[4], lf[5], lf[6], lf[7], rbl + 64);
#pragma unroll
                    for (int ks = 0; ks < 4; ks++)
#pragma unroll
                        for (int mt = 0; mt < 2; mt++) {
                            MMA16816(sc[mt][ntl],
                                     qfh[mt][ks][0], qfh[mt][ks][1],
                                     qfh[mt][ks][2], qfh[mt][ks][3],
                                     kf[2 * ks], kf[2 * ks + 1]);
                            MMA16816(sc[mt][ntl],
                                     qfh[mt][ks][0], qfh[mt][ks][1],
                                     qfh[mt][ks][2], qfh[mt][ks][3],
                                     lf[2 * ks], lf[2 * ks + 1]);
                            MMA16816(sc[mt][ntl],
                                     qfl[mt][ks][0], qfl[mt][ks][1],
                                     qfl[mt][ks][2], qfl[mt][ks][3],
                                     kf[2 * ks], kf[2 * ks + 1]);
                        }
                }

                // ---- softmax (register-resident, causal mask, no max-sub) ----
                uint32_t pah[2][4], pal[2][4];
#pragma unroll
                for (int mt = 0; mt < 2; mt++) {
#pragma unroll
                    for (int ntl = 0; ntl < 2; ntl++) {
                        int j = kt * 64 + ck * 16 + ntl * 8 + (lane & 3) * 2;
                        float e0 = ex2f(sc[mt][ntl][0] * QKS);
                        float e1 = ex2f(sc[mt][ntl][1] * QKS);
                        float e2 = ex2f(sc[mt][ntl][2] * QKS);
                        float e3 = ex2f(sc[mt][ntl][3] * QKS);
                        e0 = (j     <= rq0[mt]) ? e0 : 0.f;
                        e1 = (j + 1 <= rq0[mt]) ? e1 : 0.f;
                        e2 = (j     <= rq1[mt]) ? e2 : 0.f;
                        e3 = (j + 1 <= rq1[mt]) ? e3 : 0.f;
                        ls0[mt] += e0 + e1;
                        ls1[mt] += e2 + e3;
                        sc[mt][ntl][0] = e0; sc[mt][ntl][1] = e1;
                        sc[mt][ntl][2] = e2; sc[mt][ntl][3] = e3;
                    }
                    pah[mt][0] = packbf(sc[mt][0][0], sc[mt][0][1]);
                    pah[mt][1] = packbf(sc[mt][0][2], sc[mt][0][3]);
                    pah[mt][2] = packbf(sc[mt][1][0], sc[mt][1][1]);
                    pah[mt][3] = packbf(sc[mt][1][2], sc[mt][1][3]);
                    pal[mt][0] = packres(sc[mt][0][0], sc[mt][0][1]);
                    pal[mt][1] = packres(sc[mt][0][2], sc[mt][0][3]);
                    pal[mt][2] = packres(sc[mt][1][0], sc[mt][1][1]);
                    pal[mt][3] = packres(sc[mt][1][2], sc[mt][1][3]);
                }

                // ---- P @ V for this chunk; V via x4-trans (2 dt per instr) ----
                uint32_t rv = bbase + 18432
                            + (uint32_t)(ck * 16 + (lane & 15)) * SKB
                            + (uint32_t)(lane >> 4) * 16;
#pragma unroll
                for (int dt = 0; dt < 8; dt += 2) {
                    uint32_t v0, v1, v2, v3, w0, w1, w2, w3;
                    LDM4T(v0, v1, v2, v3, rv + dt * 16);
                    LDM4T(w0, w1, w2, w3, rv + 9216 + dt * 16);
#pragma unroll
                    for (int mt = 0; mt < 2; mt++) {
                        MMA16816(ctx[mt][dt],     pah[mt][0], pah[mt][1],
                                 pah[mt][2], pah[mt][3], v0, v1);
                        MMA16816(ctx[mt][dt],     pal[mt][0], pal[mt][1],
                                 pal[mt][2], pal[mt][3], v0, v1);
                        MMA16816(ctx[mt][dt],     pah[mt][0], pah[mt][1],
                                 pah[mt][2], pah[mt][3], w0, w1);
                        MMA16816(ctx[mt][dt + 1], pah[mt][0], pah[mt][1],
                                 pah[mt][2], pah[mt][3], v2, v3);
                        MMA16816(ctx[mt][dt + 1], pal[mt][0], pal[mt][1],
                                 pal[mt][2], pal[mt][3], v2, v3);
                        MMA16816(ctx[mt][dt + 1], pah[mt][0], pah[mt][1],
                                 pah[mt][2], pah[mt][3], w2, w3);
                    }
                }
            }
        }

        if (kt + 1 < ktiles) CP_WAIT(0);
        __syncthreads();
        buf ^= 1;
    }

    // ---- epilogue: row-sum across quad lanes, normalize, split-bf16 out ----
    const int b = bh >> 4, h = bh & 15;
#pragma unroll
    for (int mt = 0; mt < 2; mt++) {
        float l0 = ls0[mt], l1 = ls1[mt];
        l0 += __shfl_xor_sync(0xFFFFFFFFu, l0, 1);
        l0 += __shfl_xor_sync(0xFFFFFFFFu, l0, 2);
        l1 += __shfl_xor_sync(0xFFFFFFFFu, l1, 1);
        l1 += __shfl_xor_sync(0xFFFFFFFFu, l1, 2);
        const float inv0 = 1.f / l0, inv1 = 1.f / l1;

        const size_t o0 = ((size_t)(b * SEQ + rq0[mt])) * DMODEL + h * HDIM
                        + (lane & 3) * 2;
        const size_t o1 = ((size_t)(b * SEQ + rq1[mt])) * DMODEL + h * HDIM
                        + (lane & 3) * 2;
#pragma unroll
        for (int dt = 0; dt < 8; dt++) {
            float v0 = ctx[mt][dt][0] * inv0, v1 = ctx[mt][dt][1] * inv0;
            float v2 = ctx[mt][dt][2] * inv1, v3 = ctx[mt][dt][3] * inv1;
            int d = dt * 8;
            *(uint32_t*)(g_cxh + o0 + d) = packbf(v0, v1);
            *(uint32_t*)(g_cxl + o0 + d) = packres(v0, v1);
            *(uint32_t*)(g_cxh + o1 + d) = packbf(v2, v3);
            *(uint32_t*)(g_cxl + o1 + d) = packres(v2, v3);
        }
    }
}

// ---------------------------------------------------------------------------
extern "C" void kernel_launch(void* const* d_in, const int* in_sizes, int n_in,
                              void* d_out, int out_size)
{
    const float* x  = (const float*)d_in[0];
    const float* Wq = (const float*)d_in[1];
    const float* Wk = (const float*)d_in[2];
    const float* Wv = (const float*)d_in[3];
    const float* Wo = (const float*)d_in[4];
    const float* bo = (const float*)d_in[5];
    float* out = (float*)d_out;

    __nv_bfloat16 *xh, *xl, *wqh, *wql, *wkh, *wkl, *wvh, *wvl, *woh, *wol;
    __nv_bfloat16 *qh, *ql, *kh, *kl, *vh, *vl, *cxh, *cxl;
    cudaGetSymbolAddress((void**)&xh, g_xh);   cudaGetSymbolAddress((void**)&xl, g_xl);
    cudaGetSymbolAddress((void**)&wqh, g_wqh); cudaGetSymbolAddress((void**)&wql, g_wql);
    cudaGetSymbolAddress((void**)&wkh, g_wkh); cudaGetSymbolAddress((void**)&wkl, g_wkl);
    cudaGetSymbolAddress((void**)&wvh, g_wvh); cudaGetSymbolAddress((void**)&wvl, g_wvl);
    cudaGetSymbolAddress((void**)&woh, g_woh); cudaGetSymbolAddress((void**)&wol, g_wol);
    cudaGetSymbolAddress((void**)&qh, g_qh);   cudaGetSymbolAddress((void**)&ql, g_ql);
    cudaGetSymbolAddress((void**)&kh, g_kh);   cudaGetSymbolAddress((void**)&kl, g_kl);
    cudaGetSymbolAddress((void**)&vh, g_vh);   cudaGetSymbolAddress((void**)&vl, g_vl);
    cudaGetSymbolAddress((void**)&cxh, g_cxh); cudaGetSymbolAddress((void**)&cxl, g_cxl);

    cudaFuncSetAttribute(gemm_qkv, cudaFuncAttributeMaxDynamicSharedMemorySize, GM_SMEM);
    cudaFuncSetAttribute(gemm_out, cudaFuncAttributeMaxDynamicSharedMemorySize, GM_SMEM);
    cudaFuncSetAttribute(attn_hmma, cudaFuncAttributeMaxDynamicSharedMemorySize, ATT_SMEM);

    // Split x into bf16 hi/lo
    conv_split<<<MROWS * DMODEL / 4 / 256, 256>>>(
        (const float4*)x, (__nv_bfloat162*)xh, (__nv_bfloat162*)xl);
    // Transpose + split all 4 weights in one launch
    WTp wp;
    wp.w[0] = Wq; wp.th[0] = wqh; wp.tl[0] = wql;
    wp.w[1] = Wk; wp.th[1] = wkh; wp.tl[1] = wkl;
    wp.w[2] = Wv; wp.th[2] = wvh; wp.tl[2] = wvl;
    wp.w[3] = Wo; wp.th[3] = woh; wp.tl[3] = wol;
    conv_wT<<<dim3(32, 32, 4), dim3(32, 8)>>>(wp);

    // Merged QKV projections (z selects weight set)
    QKVp p;
    p.bh[0] = wqh; p.bl[0] = wql; p.ch[0] = qh; p.cl[0] = ql;
    p.bh[1] = wkh; p.bl[1] = wkl; p.ch[1] = kh; p.cl[1] = kl;
    p.bh[2] = wvh; p.bl[2] = wvl; p.ch[2] = vh; p.cl[2] = vl;
    gemm_qkv<<<dim3(DMODEL / 256, MROWS / 128, 3), 256, GM_SMEM>>>(xh, xl, p);

    // HMMA attention -> ctx split-bf16
    attn_hmma<<<dim3(SEQ / 128, BHTOT), 128, ATT_SMEM>>>();

    // Output projection + bias -> fp32 out
    gemm_out<<<dim3(DMODEL / 256, MROWS / 128), 256, GM_SMEM>>>(cxh, cxl, woh, wol, out, bo);
}

// round 13
// speedup vs baseline: 1.0707x; 1.0707x over previous
#include <cuda_runtime.h>
#include <cuda_bf16.h>
#include <stdint.h>

// Problem constants
#define BATCH   4
#define SEQ     2048
#define DMODEL  1024
#define NHEAD   16
#define HDIM    64
#define BHTOT   (BATCH * NHEAD)    // 64
#define MROWS   (BATCH * SEQ)      // 8192

// ---------------------------------------------------------------------------
// Scratch (static device globals — no allocation allowed)
// ---------------------------------------------------------------------------
__device__ __nv_bfloat16 g_xh[(size_t)MROWS * DMODEL];
__device__ __nv_bfloat16 g_xl[(size_t)MROWS * DMODEL];
__device__ __nv_bfloat16 g_wqh[(size_t)DMODEL * DMODEL];
__device__ __nv_bfloat16 g_wql[(size_t)DMODEL * DMODEL];
__device__ __nv_bfloat16 g_wkh[(size_t)DMODEL * DMODEL];
__device__ __nv_bfloat16 g_wkl[(size_t)DMODEL * DMODEL];
__device__ __nv_bfloat16 g_wvh[(size_t)DMODEL * DMODEL];
__device__ __nv_bfloat16 g_wvl[(size_t)DMODEL * DMODEL];
__device__ __nv_bfloat16 g_woh[(size_t)DMODEL * DMODEL];
__device__ __nv_bfloat16 g_wol[(size_t)DMODEL * DMODEL];
// Q/K/V in split-bf16, layout [bh][s][hd]
__device__ __nv_bfloat16 g_qh[(size_t)BHTOT * SEQ * HDIM];
__device__ __nv_bfloat16 g_ql[(size_t)BHTOT * SEQ * HDIM];
__device__ __nv_bfloat16 g_kh[(size_t)BHTOT * SEQ * HDIM];
__device__ __nv_bfloat16 g_kl[(size_t)BHTOT * SEQ * HDIM];
__device__ __nv_bfloat16 g_vh[(size_t)BHTOT * SEQ * HDIM];
__device__ __nv_bfloat16 g_vl[(size_t)BHTOT * SEQ * HDIM];
__device__ __nv_bfloat16 g_cxh[(size_t)MROWS * DMODEL];
__device__ __nv_bfloat16 g_cxl[(size_t)MROWS * DMODEL];

// ---------------------------------------------------------------------------
// Helpers
// ---------------------------------------------------------------------------
static __device__ __forceinline__ uint32_t s2u(const void* p) {
    uint32_t a;
    asm("{ .reg .u64 t; cvta.to.shared.u64 t, %1; cvt.u32.u64 %0, t; }"
        : "=r"(a) : "l"(p));
    return a;
}

#define CPA16(dst, src) \
    asm volatile("cp.async.cg.shared.global [%0], [%1], 16;" :: "r"(dst), "l"(src))
#define CP_COMMIT() asm volatile("cp.async.commit_group;" ::: "memory")
#define CP_WAIT(n)  asm volatile("cp.async.wait_group %0;" :: "n"(n) : "memory")

#define LDM4(r0, r1, r2, r3, a) \
    asm volatile("ldmatrix.sync.aligned.m8n8.x4.shared.b16 {%0,%1,%2,%3}, [%4];" \
                 : "=r"(r0), "=r"(r1), "=r"(r2), "=r"(r3) : "r"(a))
#define LDM2(r0, r1, a) \
    asm volatile("ldmatrix.sync.aligned.m8n8.x2.shared.b16 {%0,%1}, [%2];" \
                 : "=r"(r0), "=r"(r1) : "r"(a))
#define LDM4T(r0, r1, r2, r3, a) \
    asm volatile("ldmatrix.sync.aligned.m8n8.x4.trans.shared.b16 {%0,%1,%2,%3}, [%4];" \
                 : "=r"(r0), "=r"(r1), "=r"(r2), "=r"(r3) : "r"(a))

#define MMA16816(c, a0, a1, a2, a3, b0, b1) \
    asm volatile("mma.sync.aligned.m16n8k16.row.col.f32.bf16.bf16.f32 " \
                 "{%0,%1,%2,%3}, {%4,%5,%6,%7}, {%8,%9}, {%0,%1,%2,%3};" \
                 : "+f"((c)[0]), "+f"((c)[1]), "+f"((c)[2]), "+f"((c)[3]) \
                 : "r"(a0), "r"(a1), "r"(a2), "r"(a3), "r"(b0), "r"(b1))

static __device__ __forceinline__ float ex2f(float x) {
    float y;
    asm("ex2.approx.ftz.f32 %0, %1;" : "=f"(y) : "f"(x));
    return y;
}
static __device__ __forceinline__ uint32_t packbf(float a, float b) {
    __nv_bfloat162 t = __floats2bfloat162_rn(a, b);
    return *reinterpret_cast<uint32_t*>(&t);
}
static __device__ __forceinline__ uint32_t packres(float a, float b) {
    float ra = a - __bfloat162float(__float2bfloat16(a));
    float rb = b - __bfloat162float(__float2bfloat16(b));
    return packbf(ra, rb);
}

// XOR swizzle for 64B-row tiles: row r, 16B-chunk c (0..3)
static __device__ __forceinline__ uint32_t swz64(int r, int c) {
    return (uint32_t)(r * 64 + ((c ^ ((r >> 1) & 3)) << 4));
}

// ---------------------------------------------------------------------------
// Pre-pass: split fp32 -> bf16 hi/lo (elementwise)
// ---------------------------------------------------------------------------
__global__ void __launch_bounds__(256)
conv_split(const float4* __restrict__ X, __nv_bfloat162* __restrict__ H,
           __nv_bfloat162* __restrict__ L)
{
    int i = blockIdx.x * 256 + threadIdx.x;
    float4 v = X[i];
    H[2 * i]     = __floats2bfloat162_rn(v.x, v.y);
    H[2 * i + 1] = __floats2bfloat162_rn(v.z, v.w);
    uint32_t l0 = packres(v.x, v.y), l1 = packres(v.z, v.w);
    L[2 * i]     = *reinterpret_cast<__nv_bfloat162*>(&l0);
    L[2 * i + 1] = *reinterpret_cast<__nv_bfloat162*>(&l1);
}

// ---------------------------------------------------------------------------
// Pre-pass: W[k][n] fp32 -> Wt[n][k] bf16 hi/lo (transpose + split),
// all 4 weight matrices in one launch (blockIdx.z selects).
// ---------------------------------------------------------------------------
struct WTp {
    const float* w[4];
    __nv_bfloat16* th[4];
    __nv_bfloat16* tl[4];
};

__global__ void __launch_bounds__(256)
conv_wT(WTp p)
{
    __shared__ float t[32][33];
    const int z = blockIdx.z;
    const float* __restrict__ W = p.w[z];
    __nv_bfloat16* __restrict__ Th = p.th[z];
    __nv_bfloat16* __restrict__ Tl = p.tl[z];
    const int n0 = blockIdx.x * 32, k0 = blockIdx.y * 32;
    const int tx = threadIdx.x, ty = threadIdx.y;   // 32 x 8
#pragma unroll
    for (int i = 0; i < 4; i++)
        t[ty + i * 8][tx] = W[(size_t)(k0 + ty + i * 8) * DMODEL + n0 + tx];
    __syncthreads();
#pragma unroll
    for (int i = 0; i < 4; i++) {
        float v = t[tx][ty + i * 8];
        __nv_bfloat16 h = __float2bfloat16(v);
        size_t o = (size_t)(n0 + ty + i * 8) * DMODEL + k0 + tx;
        Th[o] = h;
        Tl[o] = __float2bfloat16(v - __bfloat162float(h));
    }
}

// ---------------------------------------------------------------------------
// HMMA split-bf16 GEMM body (R11 winner, reverted from R12 regression):
// 128x128 CTA tile, 8 warps (2x4), warp 64x32, XOR-swizzled 64B rows,
// 3-stage cp.async ring, ONE sync/stage, loads issued BEFORE the wait,
// 2 CTAs/SM (latency hiding across CTAs is load-bearing).
// ---------------------------------------------------------------------------
#define TILE_B  (128 * 64)                 // 8192 bytes per tile (64B rows)
#define STAGE_B (4 * TILE_B)               // Ah, Al, Bh, Bl = 32768
#define GM_SMEM (3 * STAGE_B)              // 98304

template <bool SCAT>
static __device__ __forceinline__ void
gemm_body(const __nv_bfloat16* __restrict__ Ah, const __nv_bfloat16* __restrict__ Al,
          const __nv_bfloat16* __restrict__ Bh, const __nv_bfloat16* __restrict__ Bl,
          float* __restrict__ C, const float* __restrict__ bias,
          __nv_bfloat16* __restrict__ Ch, __nv_bfloat16* __restrict__ Cl)
{
    extern __shared__ char smem[];
    const uint32_t sb = s2u(smem);
    const int tid = threadIdx.x;
    const int wid = tid >> 5, lane = tid & 31;
    const int warp_m = wid & 1;
    const int warp_n = wid >> 1;
    const int bm = blockIdx.y * 128;
    const int bn = blockIdx.x * 128;

    float acc[4][4][4];
#pragma unroll
    for (int i = 0; i < 4; i++)
#pragma unroll
        for (int j = 0; j < 4; j++)
#pragma unroll
            for (int q = 0; q < 4; q++) acc[i][j][q] = 0.f;

    auto load_stage = [&](int s, int buf) {
        const int k0 = s * 32;
        const uint32_t base = sb + buf * STAGE_B;
#pragma unroll
        for (int i = 0; i < 2; i++) {
            int idx = tid + i * 256;
            int r = idx >> 2, c = idx & 3;
            uint32_t off = swz64(r, c);
            const size_t ga = (size_t)(bm + r) * DMODEL + k0 + c * 8;
            const size_t gb = (size_t)(bn + r) * DMODEL + k0 + c * 8;
            CPA16(base + off,              Ah + ga);
            CPA16(base + TILE_B + off,     Al + ga);
            CPA16(base + 2 * TILE_B + off, Bh + gb);
            CPA16(base + 3 * TILE_B + off, Bl + gb);
        }
        CP_COMMIT();
    };

    load_stage(0, 0);

    const int a_row = warp_m * 64 + (lane & 15);
    const int a_c   = (lane >> 4);
    const int b_row = warp_n * 32 + (lane & 7);
    const int b_c   = ((lane >> 3) & 1);

    const int NSTAGE = DMODEL / 32;   // 32

    for (int s = 0; s < NSTAGE; s++) {
        if (s + 1 < NSTAGE) {
            load_stage(s + 1, (s + 1) % 3);
            CP_WAIT(1);
        } else {
            CP_WAIT(0);
        }
        __syncthreads();

        const uint32_t base = sb + (s % 3) * STAGE_B;
#pragma unroll
        for (int kk = 0; kk < 2; kk++) {
            uint32_t ah[4][4], al[4][4], bh[4][2], bl[4][2];
#pragma unroll
            for (int mt = 0; mt < 4; mt++) {
                uint32_t ra = base + swz64(a_row + mt * 16, a_c + kk * 2);
                LDM4(ah[mt][0], ah[mt][1], ah[mt][2], ah[mt][3], ra);
                LDM4(al[mt][0], al[mt][1], al[mt][2], al[mt][3], ra + TILE_B);
            }
#pragma unroll
            for (int nt = 0; nt < 4; nt++) {
                uint32_t rb = base + 2 * TILE_B + swz64(b_row + nt * 8, b_c + kk * 2);
                LDM2(bh[nt][0], bh[nt][1], rb);
                LDM2(bl[nt][0], bl[nt][1], rb + TILE_B);
            }
#pragma unroll
            for (int mt = 0; mt < 4; mt++)
#pragma unroll
                for (int nt = 0; nt < 4; nt++) {
                    MMA16816(acc[mt][nt], ah[mt][0], ah[mt][1], ah[mt][2], ah[mt][3],
                             bh[nt][0], bh[nt][1]);
                    MMA16816(acc[mt][nt], ah[mt][0], ah[mt][1], ah[mt][2], ah[mt][3],
                             bl[nt][0], bl[nt][1]);
                    MMA16816(acc[mt][nt], al[mt][0], al[mt][1], al[mt][2], al[mt][3],
                             bh[nt][0], bh[nt][1]);
                }
        }
    }

    const int r0 = bm + warp_m * 64 + (lane >> 2);
    const int c0 = bn + warp_n * 32 + (lane & 3) * 2;
#pragma unroll
    for (int mt = 0; mt < 4; mt++) {
#pragma unroll
        for (int nt = 0; nt < 4; nt++) {
            const int row = r0 + mt * 16;
            const int col = c0 + nt * 8;
            if (SCAT) {
                const int h = col >> 6, hd = col & 63;
#pragma unroll
                for (int half = 0; half < 2; half++) {
                    const int rr = row + half * 8;
                    const int b = rr >> 11, sq = rr & 2047;
                    size_t o = (((size_t)(b * NHEAD + h) * SEQ + sq) * HDIM + hd);
                    float v0 = acc[mt][nt][2 * half], v1 = acc[mt][nt][2 * half + 1];
                    *(uint32_t*)(Ch + o) = packbf(v0, v1);
                    *(uint32_t*)(Cl + o) = packres(v0, v1);
                }
            } else {
                float2 bv = *(const float2*)(bias + col);
#pragma unroll
                for (int half = 0; half < 2; half++) {
                    const int rr = row + half * 8;
                    float* dst = C + (size_t)rr * DMODEL + col;
                    *(float2*)dst = make_float2(acc[mt][nt][2 * half] + bv.x,
                                                acc[mt][nt][2 * half + 1] + bv.y);
                }
            }
        }
    }
}

struct QKVp {
    const __nv_bfloat16* bh[3];
    const __nv_bfloat16* bl[3];
    __nv_bfloat16* ch[3];
    __nv_bfloat16* cl[3];
};

__global__ void __launch_bounds__(256, 2)
gemm_qkv(const __nv_bfloat16* __restrict__ Ah, const __nv_bfloat16* __restrict__ Al,
         QKVp p)
{
    const int z = blockIdx.z;
    gemm_body<true>(Ah, Al, p.bh[z], p.bl[z], nullptr, nullptr, p.ch[z], p.cl[z]);
}

__global__ void __launch_bounds__(256, 2)
gemm_out(const __nv_bfloat16* __restrict__ Ah, const __nv_bfloat16* __restrict__ Al,
         const __nv_bfloat16* __restrict__ Bh, const __nv_bfloat16* __restrict__ Bl,
         float* __restrict__ C, const float* __restrict__ bias)
{
    gemm_body<false>(Ah, Al, Bh, Bl, C, bias, nullptr, nullptr);
}

// ---------------------------------------------------------------------------
// HMMA causal flash attention, split-bf16 (3-term), 4 warps x 32 query rows.
// Per-warp FULL/DIAGONAL tile split: tiles entirely below the diagonal run a
// straight-line unmasked fully-unrolled path (no break, no mask ternaries ->
// better cross-chunk scheduling); only the warp's diagonal tile runs the
// masked per-chunk path. Warp-uniform branch, syncthreads outside. K/V
// double-buffered, LPT scheduling. Emits ctx as split-bf16 ([b][s][d]).
// ---------------------------------------------------------------------------
#define QKS 0.18033688f   // log2(e) / sqrt(64)
#define SKB 144           // padded row stride in bytes (72 bf16)
#define AQH_OFF 0
#define AQL_OFF 18432
#define KV_OFF  36864     // start of KV buffers
#define KVB     36864     // bytes per KV buffer (KH, KL, VH, VL @ 9216 each)
#define ATT_SMEM (KV_OFF + 2 * KVB)   // 110592

__global__ void __launch_bounds__(128, 2)
attn_hmma()
{
    extern __shared__ char smem[];
    const uint32_t sb = s2u(smem);
    const int tid = threadIdx.x, wid = tid >> 5, lane = tid & 31;
    const int qt = (int)(gridDim.x - 1 - blockIdx.x);   // LPT: long CTAs first
    const int bh = blockIdx.y;

    // async-load Q tile (hi+lo): 128 rows x 64 bf16, 128 threads
    {
        const __nv_bfloat16* qh = g_qh + ((size_t)bh * SEQ + qt * 128) * HDIM;
        const __nv_bfloat16* ql = g_ql + ((size_t)bh * SEQ + qt * 128) * HDIM;
#pragma unroll
        for (int i = 0; i < 8; i++) {
            int c = tid + i * 128;
            int r = c >> 3, ch = c & 7;
            uint32_t o = (uint32_t)(r * SKB + ch * 16);
            CPA16(sb + AQH_OFF + o, qh + r * HDIM + ch * 8);
            CPA16(sb + AQL_OFF + o, ql + r * HDIM + ch * 8);
        }
        CP_COMMIT();
    }

    auto load_kv = [&](int kt, int buf) {
        const size_t gbase = ((size_t)bh * SEQ + kt * 64) * HDIM;
        const uint32_t base = sb + KV_OFF + buf * KVB;
#pragma unroll
        for (int i = 0; i < 4; i++) {
            int c = tid + i * 128;            // 0..511
            int r = c >> 3, ch = c & 7;
            uint32_t o = (uint32_t)(r * SKB + ch * 16);
            const int g = r * HDIM + ch * 8;
            CPA16(base + o,             g_kh + gbase + g);
            CPA16(base + 9216 + o,      g_kl + gbase + g);
            CPA16(base + 18432 + o,     g_vh + gbase + g);
            CPA16(base + 27648 + o,     g_vl + gbase + g);
        }
        CP_COMMIT();
    };

    const int ktiles = 2 * qt + 2;
    load_kv(0, 0);
    CP_WAIT(0);
    __syncthreads();

    // Q fragments: 2 m16 tiles per warp (rows wid*32 + mt*16), never overwritten
    uint32_t qfh[2][4][4], qfl[2][4][4];
#pragma unroll
    for (int mt = 0; mt < 2; mt++) {
        uint32_t ra = sb + AQH_OFF
                    + (uint32_t)(wid * 32 + mt * 16 + (lane & 15)) * SKB
                    + (uint32_t)(lane >> 4) * 16;
        uint32_t rl = ra + (AQL_OFF - AQH_OFF);
#pragma unroll
        for (int ks = 0; ks < 4; ks++) {
            LDM4(qfh[mt][ks][0], qfh[mt][ks][1], qfh[mt][ks][2], qfh[mt][ks][3],
                 ra + ks * 32);
            LDM4(qfl[mt][ks][0], qfl[mt][ks][1], qfl[mt][ks][2], qfl[mt][ks][3],
                 rl + ks * 32);
        }
    }

    float ctx[2][8][4];
#pragma unroll
    for (int mt = 0; mt < 2; mt++)
#pragma unroll
        for (int d = 0; d < 8; d++)
#pragma unroll
            for (int q = 0; q < 4; q++) ctx[mt][d][q] = 0.f;
    float ls0[2] = {0.f, 0.f}, ls1[2] = {0.f, 0.f};

    const int row_lo = qt * 128 + wid * 32;        // warp's lowest query row
    const int row_hi = row_lo + 31;
    int rq0[2], rq1[2];
#pragma unroll
    for (int mt = 0; mt < 2; mt++) {
        rq0[mt] = row_lo + mt * 16 + (lane >> 2);
        rq1[mt] = rq0[mt] + 8;
    }

    int buf = 0;
    for (int kt = 0; kt < ktiles; kt++) {
        if (kt + 1 < ktiles) load_kv(kt + 1, buf ^ 1);

        const uint32_t bbase = sb + KV_OFF + buf * KVB;

        // process one 16-key chunk; MASK known at compile time per call site
        auto do_chunk = [&](int ck, bool mask) {
            // ---- QK^T for this chunk: 2 nt x 2 mt ----
            float sc[2][2][4];
#pragma unroll
            for (int mt = 0; mt < 2; mt++)
#pragma unroll
                for (int ntl = 0; ntl < 2; ntl++)
#pragma unroll
                    for (int q = 0; q < 4; q++) sc[mt][ntl][q] = 0.f;

#pragma unroll
            for (int ntl = 0; ntl < 2; ntl++) {
                const int nt = ck * 2 + ntl;
                uint32_t kf[8], lf[8];
                uint32_t rb = bbase + (uint32_t)(nt * 8 + (lane & 7)) * SKB
                            + (uint32_t)(lane >> 3) * 16;
                LDM4(kf[0], kf[1], kf[2], kf[3], rb);
                LDM4(kf[4], kf[5], kf[6], kf[7], rb + 64);
                uint32_t rbl = rb + 9216;
                LDM4(lf[0], lf[1], lf[2], lf[3], rbl);
                LDM4(lf[4], lf[5], lf[6], lf[7], rbl + 64);
#pragma unroll
                for (int ks = 0; ks < 4; ks++)
#pragma unroll
                    for (int mt = 0; mt < 2; mt++) {
                        MMA16816(sc[mt][ntl],
                                 qfh[mt][ks][0], qfh[mt][ks][1],
                                 qfh[mt][ks][2], qfh[mt][ks][3],
                                 kf[2 * ks], kf[2 * ks + 1]);
                        MMA16816(sc[mt][ntl],
                                 qfh[mt][ks][0], qfh[mt][ks][1],
                                 qfh[mt][ks][2], qfh[mt][ks][3],
                                 lf[2 * ks], lf[2 * ks + 1]);
                        MMA16816(sc[mt][ntl],
                                 qfl[mt][ks][0], qfl[mt][ks][1],
                                 qfl[mt][ks][2], qfl[mt][ks][3],
                                 kf[2 * ks], kf[2 * ks + 1]);
                    }
            }

            // ---- softmax (register-resident; mask only on diagonal tiles) ----
            uint32_t pah[2][4], pal[2][4];
#pragma unroll
            for (int mt = 0; mt < 2; mt++) {
#pragma unroll
                for (int ntl = 0; ntl < 2; ntl++) {
                    float e0 = ex2f(sc[mt][ntl][0] * QKS);
                    float e1 = ex2f(sc[mt][ntl][1] * QKS);
                    float e2 = ex2f(sc[mt][ntl][2] * QKS);
                    float e3 = ex2f(sc[mt][ntl][3] * QKS);
                    if (mask) {
                        int j = kt * 64 + ck * 16 + ntl * 8 + (lane & 3) * 2;
                        e0 = (j     <= rq0[mt]) ? e0 : 0.f;
                        e1 = (j + 1 <= rq0[mt]) ? e1 : 0.f;
                        e2 = (j     <= rq1[mt]) ? e2 : 0.f;
                        e3 = (j + 1 <= rq1[mt]) ? e3 : 0.f;
                    }
                    ls0[mt] += e0 + e1;
                    ls1[mt] += e2 + e3;
                    sc[mt][ntl][0] = e0; sc[mt][ntl][1] = e1;
                    sc[mt][ntl][2] = e2; sc[mt][ntl][3] = e3;
                }
                pah[mt][0] = packbf(sc[mt][0][0], sc[mt][0][1]);
                pah[mt][1] = packbf(sc[mt][0][2], sc[mt][0][3]);
                pah[mt][2] = packbf(sc[mt][1][0], sc[mt][1][1]);
                pah[mt][3] = packbf(sc[mt][1][2], sc[mt][1][3]);
                pal[mt][0] = packres(sc[mt][0][0], sc[mt][0][1]);
                pal[mt][1] = packres(sc[mt][0][2], sc[mt][0][3]);
                pal[mt][2] = packres(sc[mt][1][0], sc[mt][1][1]);
                pal[mt][3] = packres(sc[mt][1][2], sc[mt][1][3]);
            }

            // ---- P @ V for this chunk; V via x4-trans (2 dt per instr) ----
            uint32_t rv = bbase + 18432
                        + (uint32_t)(ck * 16 + (lane & 15)) * SKB
                        + (uint32_t)(lane >> 4) * 16;
#pragma unroll
            for (int dt = 0; dt < 8; dt += 2) {
                uint32_t v0, v1, v2, v3, w0, w1, w2, w3;
                LDM4T(v0, v1, v2, v3, rv + dt * 16);
                LDM4T(w0, w1, w2, w3, rv + 9216 + dt * 16);
#pragma unroll
                for (int mt = 0; mt < 2; mt++) {
                    MMA16816(ctx[mt][dt],     pah[mt][0], pah[mt][1],
                             pah[mt][2], pah[mt][3], v0, v1);
                    MMA16816(ctx[mt][dt],     pal[mt][0], pal[mt][1],
                             pal[mt][2], pal[mt][3], v0, v1);
                    MMA16816(ctx[mt][dt],     pah[mt][0], pah[mt][1],
                             pah[mt][2], pah[mt][3], w0, w1);
                    MMA16816(ctx[mt][dt + 1], pah[mt][0], pah[mt][1],
                             pah[mt][2], pah[mt][3], v2, v3);
                    MMA16816(ctx[mt][dt + 1], pal[mt][0], pal[mt][1],
                             pal[mt][2], pal[mt][3], v2, v3);
                    MMA16816(ctx[mt][dt + 1], pah[mt][0], pah[mt][1],
                             pah[mt][2], pah[mt][3], w2, w3);
                }
            }
        };

        if (kt * 64 + 63 <= row_lo) {
            // full tile: no masking possible for any of this warp's rows
#pragma unroll
            for (int ck = 0; ck < 4; ck++) do_chunk(ck, false);
        } else if (kt * 64 <= row_hi) {
            // diagonal tile: masked, with per-chunk causal skip
            for (int ck = 0; ck < 4; ck++) {
                if (kt * 64 + ck * 16 > row_hi) break;
                do_chunk(ck, true);
            }
        }

        if (kt + 1 < ktiles) CP_WAIT(0);
        __syncthreads();
        buf ^= 1;
    }

    // ---- epilogue: row-sum across quad lanes, normalize, split-bf16 out ----
    const int b = bh >> 4, h = bh & 15;
#pragma unroll
    for (int mt = 0; mt < 2; mt++) {
        float l0 = ls0[mt], l1 = ls1[mt];
        l0 += __shfl_xor_sync(0xFFFFFFFFu, l0, 1);
        l0 += __shfl_xor_sync(0xFFFFFFFFu, l0, 2);
        l1 += __shfl_xor_sync(0xFFFFFFFFu, l1, 1);
        l1 += __shfl_xor_sync(0xFFFFFFFFu, l1, 2);
        const float inv0 = 1.f / l0, inv1 = 1.f / l1;

        const size_t o0 = ((size_t)(b * SEQ + rq0[mt])) * DMODEL + h * HDIM
                        + (lane & 3) * 2;
        const size_t o1 = ((size_t)(b * SEQ + rq1[mt])) * DMODEL + h * HDIM
                        + (lane & 3) * 2;
#pragma unroll
        for (int dt = 0; dt < 8; dt++) {
            float v0 = ctx[mt][dt][0] * inv0, v1 = ctx[mt][dt][1] * inv0;
            float v2 = ctx[mt][dt][2] * inv1, v3 = ctx[mt][dt][3] * inv1;
            int d = dt * 8;
            *(uint32_t*)(g_cxh + o0 + d) = packbf(v0, v1);
            *(uint32_t*)(g_cxl + o0 + d) = packres(v0, v1);
            *(uint32_t*)(g_cxh + o1 + d) = packbf(v2, v3);
            *(uint32_t*)(g_cxl + o1 + d) = packres(v2, v3);
        }
    }
}

// ---------------------------------------------------------------------------
extern "C" void kernel_launch(void* const* d_in, const int* in_sizes, int n_in,
                              void* d_out, int out_size)
{
    const float* x  = (const float*)d_in[0];
    const float* Wq = (const float*)d_in[1];
    const float* Wk = (const float*)d_in[2];
    const float* Wv = (const float*)d_in[3];
    const float* Wo = (const float*)d_in[4];
    const float* bo = (const float*)d_in[5];
    float* out = (float*)d_out;

    __nv_bfloat16 *xh, *xl, *wqh, *wql, *wkh, *wkl, *wvh, *wvl, *woh, *wol;
    __nv_bfloat16 *qh, *ql, *kh, *kl, *vh, *vl, *cxh, *cxl;
    cudaGetSymbolAddress((void**)&xh, g_xh);   cudaGetSymbolAddress((void**)&xl, g_xl);
    cudaGetSymbolAddress((void**)&wqh, g_wqh); cudaGetSymbolAddress((void**)&wql, g_wql);
    cudaGetSymbolAddress((void**)&wkh, g_wkh); cudaGetSymbolAddress((void**)&wkl, g_wkl);
    cudaGetSymbolAddress((void**)&wvh, g_wvh); cudaGetSymbolAddress((void**)&wvl, g_wvl);
    cudaGetSymbolAddress((void**)&woh, g_woh); cudaGetSymbolAddress((void**)&wol, g_wol);
    cudaGetSymbolAddress((void**)&qh, g_qh);   cudaGetSymbolAddress((void**)&ql, g_ql);
    cudaGetSymbolAddress((void**)&kh, g_kh);   cudaGetSymbolAddress((void**)&kl, g_kl);
    cudaGetSymbolAddress((void**)&vh, g_vh);   cudaGetSymbolAddress((void**)&vl, g_vl);
    cudaGetSymbolAddress((void**)&cxh, g_cxh); cudaGetSymbolAddress((void**)&cxl, g_cxl);

    cudaFuncSetAttribute(gemm_qkv, cudaFuncAttributeMaxDynamicSharedMemorySize, GM_SMEM);
    cudaFuncSetAttribute(gemm_out, cudaFuncAttributeMaxDynamicSharedMemorySize, GM_SMEM);
    cudaFuncSetAttribute(attn_hmma, cudaFuncAttributeMaxDynamicSharedMemorySize, ATT_SMEM);

    // Split x into bf16 hi/lo
    conv_split<<<MROWS * DMODEL / 4 / 256, 256>>>(
        (const float4*)x, (__nv_bfloat162*)xh, (__nv_bfloat162*)xl);
    // Transpose + split all 4 weights in one launch
    WTp wp;
    wp.w[0] = Wq; wp.th[0] = wqh; wp.tl[0] = wql;
    wp.w[1] = Wk; wp.th[1] = wkh; wp.tl[1] = wkl;
    wp.w[2] = Wv; wp.th[2] = wvh; wp.tl[2] = wvl;
    wp.w[3] = Wo; wp.th[3] = woh; wp.tl[3] = wol;
    conv_wT<<<dim3(32, 32, 4), dim3(32, 8)>>>(wp);

    // Merged QKV projections (z selects weight set)
    QKVp p;
    p.bh[0] = wqh; p.bl[0] = wql; p.ch[0] = qh; p.cl[0] = ql;
    p.bh[1] = wkh; p.bl[1] = wkl; p.ch[1] = kh; p.cl[1] = kl;
    p.bh[2] = wvh; p.bl[2] = wvl; p.ch[2] = vh; p.cl[2] = vl;
    gemm_qkv<<<dim3(DMODEL / 128, MROWS / 128, 3), 256, GM_SMEM>>>(xh, xl, p);

    // HMMA attention -> ctx split-bf16
    attn_hmma<<<dim3(SEQ / 128, BHTOT), 128, ATT_SMEM>>>();

    // Output projection + bias -> fp32 out
    gemm_out<<<dim3(DMODEL / 128, MROWS / 128), 256, GM_SMEM>>>(cxh, cxl, woh, wol, out, bo);
}